// round 7
// baseline (speedup 1.0000x reference)
#include <cuda_runtime.h>

#define S_LEN   2048
#define NCH     64
#define NB      16
#define CHUNK   64
#define NSC     (S_LEN / CHUNK)        // 32 sample-chunks
#define PLI_THREADS 256
#define NWARPS  (PLI_THREADS / 32)     // 8
#define FFT_THREADS 512
#define N_PLI_BLOCKS (NSC * NB)        // 512  (single wave on 148 SMs @ 4/SM)

// Scratch (static __device__ allocation — allowed by harness rules)
__device__ unsigned g_theta[NB * NCH * S_LEN];    // 8 MB quantized phase
__device__ int      g_cnt[NB * NCH * NCH];        // 256 KB counters
__device__ int      g_done;                       // finalize gate

// 136 upper-triangle 4x4-tile coords, packed (ti<<4)|tj
__constant__ unsigned char c_tile[136] = {
 0x00,0x01,0x02,0x03,0x04,0x05,0x06,0x07,0x08,0x09,0x0A,0x0B,0x0C,0x0D,0x0E,0x0F,
 0x11,0x12,0x13,0x14,0x15,0x16,0x17,0x18,0x19,0x1A,0x1B,0x1C,0x1D,0x1E,0x1F,
 0x22,0x23,0x24,0x25,0x26,0x27,0x28,0x29,0x2A,0x2B,0x2C,0x2D,0x2E,0x2F,
 0x33,0x34,0x35,0x36,0x37,0x38,0x39,0x3A,0x3B,0x3C,0x3D,0x3E,0x3F,
 0x44,0x45,0x46,0x47,0x48,0x49,0x4A,0x4B,0x4C,0x4D,0x4E,0x4F,
 0x55,0x56,0x57,0x58,0x59,0x5A,0x5B,0x5C,0x5D,0x5E,0x5F,
 0x66,0x67,0x68,0x69,0x6A,0x6B,0x6C,0x6D,0x6E,0x6F,
 0x77,0x78,0x79,0x7A,0x7B,0x7C,0x7D,0x7E,0x7F,
 0x88,0x89,0x8A,0x8B,0x8C,0x8D,0x8E,0x8F,
 0x99,0x9A,0x9B,0x9C,0x9D,0x9E,0x9F,
 0xAA,0xAB,0xAC,0xAD,0xAE,0xAF,
 0xBB,0xBC,0xBD,0xBE,0xBF,
 0xCC,0xCD,0xCE,0xCF,
 0xDD,0xDE,0xDF,
 0xEE,0xEF,
 0xFF };

// shared-memory index padding for the FFT stages
__device__ __forceinline__ int SPAD(int i) { return i + (i >> 3); }
#define FFT_PADDED 2304

// ---------------------------------------------------------------------------
// Radix-4 Stockham autosort FFT (N = 2048 = 2 * 4^5), DIF, natural order.
// ---------------------------------------------------------------------------
__device__ __forceinline__ float2 cmul(float2 a, float2 b) {
    return make_float2(fmaf(a.x, b.x, -a.y * b.y),
                       fmaf(a.x, b.y,  a.y * b.x));
}

__device__ __forceinline__ void stage_r2_fwd(const float2* __restrict__ src,
                                             float2* __restrict__ dst,
                                             const float2* __restrict__ tw,
                                             int tid) {
    for (int p = tid; p < 1024; p += FFT_THREADS) {
        float2 w = tw[p];
        float2 a = src[SPAD(p)];
        float2 b = src[SPAD(p + 1024)];
        dst[SPAD(2 * p)]     = make_float2(a.x + b.x, a.y + b.y);
        dst[SPAD(2 * p + 1)] = cmul(w, make_float2(a.x - b.x, a.y - b.y));
    }
}

template<int L, int LOG2M, bool INV>
__device__ __forceinline__ void stage_r4(const float2* __restrict__ src,
                                         float2* __restrict__ dst,
                                         const float2* __restrict__ tw,
                                         int tid) {
    constexpr int M   = 1 << LOG2M;
    constexpr int TWS = 512 / L;
    for (int t = tid; t < 512; t += FFT_THREADS) {
        const int p = t >> LOG2M;
        const int q = t & (M - 1);
        const int ib = q + M * p;
        float2 a = src[SPAD(ib)];
        float2 b = src[SPAD(ib + M * L)];
        float2 c = src[SPAD(ib + 2 * M * L)];
        float2 d = src[SPAD(ib + 3 * M * L)];

        float2 w1 = tw[p * TWS];
        float2 w2 = tw[2 * p * TWS];
        if (INV) { w1.y = -w1.y; w2.y = -w2.y; }
        float2 w3 = cmul(w1, w2);

        float2 t0 = make_float2(a.x + c.x, a.y + c.y);
        float2 t1 = make_float2(a.x - c.x, a.y - c.y);
        float2 t2 = make_float2(b.x + d.x, b.y + d.y);
        float2 e  = make_float2(b.x - d.x, b.y - d.y);
        float2 t3 = INV ? make_float2(-e.y,  e.x)
                        : make_float2( e.y, -e.x);

        const int ob = q + 4 * M * p;
        dst[SPAD(ob)]         = make_float2(t0.x + t2.x, t0.y + t2.y);
        dst[SPAD(ob + M)]     = cmul(w1, make_float2(t1.x + t3.x, t1.y + t3.y));
        dst[SPAD(ob + 2 * M)] = cmul(w2, make_float2(t0.x - t2.x, t0.y - t2.y));
        dst[SPAD(ob + 3 * M)] = cmul(w3, make_float2(t1.x - t3.x, t1.y - t3.y));
    }
}

__device__ __forceinline__ void ifft_tail(float2* __restrict__ X,
                                          float2* __restrict__ Y,
                                          const float2* __restrict__ tw,
                                          int tid) {
    stage_r4<256, 1, true>(X, Y, tw, tid);  __syncthreads();
    stage_r4< 64, 3, true>(Y, X, tw, tid);  __syncthreads();
    stage_r4< 16, 5, true>(X, Y, tw, tid);  __syncthreads();
    stage_r4<  4, 7, true>(Y, X, tw, tid);  __syncthreads();
    stage_r4<  1, 9, true>(X, Y, tw, tid);  __syncthreads();
}

// Diamond angle, quantized so a half-turn == 2^31 exactly (mod 2^32).
// Monotone map of atan2(y,x); wrapped-difference sign tests are invariant
// under any monotone circular reparameterization with exact antipode offset.
__device__ __forceinline__ unsigned diamond_u32(float x, float y) {
    float r = __fdividef(y, fabsf(x) + fabsf(y));     // [-1,1]
    float d;
    if (x >= 0.0f) d = r;
    else           d = (y >= 0.0f) ? (2.0f - r) : (-2.0f - r);
    return (unsigned)__float2int_rn(d * 1073741824.0f);   // * 2^30
}

// ---------------------------------------------------------------------------
// Kernel 1: Hilbert analytic signal -> quantized phase, 2 channels per block.
// One packed forward FFT; unpack + Hilbert filter fused with the degenerate
// first inverse stage; two 5-stage inverse tails; diamond-angle quantize.
// Positive real scale factors dropped (signs are scale-invariant).
// Also zeroes g_cnt / g_done for the pli pass (stream-ordered before it).
// ---------------------------------------------------------------------------
__global__ __launch_bounds__(FFT_THREADS)
void hilbert_kernel(const float* __restrict__ x) {
    extern __shared__ float2 smem[];
    float2* A  = smem;
    float2* B  = smem + FFT_PADDED;
    float2* C  = smem + 2 * FFT_PADDED;
    float2* tw = smem + 3 * FFT_PADDED;

    const int tid = threadIdx.x;
    const int blk = blockIdx.x;                 // 0..511
    const int ch0 = 2 * blk;

    if (tid < 128) g_cnt[blk * 128 + tid] = 0;
    if (blk == 0 && tid == 0) g_done = 0;

    const float* __restrict__ x0 = x + (size_t)ch0 * S_LEN;
    const float* __restrict__ x1 = x0 + S_LEN;

    // twiddles (fast intrinsic: args <= 2*pi, abs err ~2^-21 -> phase error
    // ~1e-5 rad, sign-flip probability negligible vs 1e-3 tolerance)
    for (int k = tid; k < 1024; k += FFT_THREADS) {
        float sn, cs;
        __sincosf((-6.283185307179586f / 2048.0f) * (float)k, &sn, &cs);
        tw[k] = make_float2(cs, sn);
    }
    for (int i = tid; i < S_LEN; i += FFT_THREADS)
        A[SPAD(i)] = make_float2(x0[i], x1[i]);
    __syncthreads();

    // forward FFT: result in A (natural order)
    stage_r2_fwd(A, B, tw, tid);               __syncthreads();
    stage_r4<256, 1, false>(B, A, tw, tid);    __syncthreads();
    stage_r4< 64, 3, false>(A, B, tw, tid);    __syncthreads();
    stage_r4< 16, 5, false>(B, A, tw, tid);    __syncthreads();
    stage_r4<  4, 7, false>(A, B, tw, tid);    __syncthreads();
    stage_r4<  1, 9, false>(B, A, tw, tid);    __syncthreads();

    // Unpack + Hilbert filter + fused (degenerate) inverse stage-1
    for (int p = tid; p < 1024; p += FFT_THREADS) {
        float2 zk = A[SPAD(p)];
        float2 zm = A[SPAD((S_LEN - p) & (S_LEN - 1))];
        float  h  = (p == 0) ? 1.0f : 2.0f;
        float2 G0 = make_float2(h * (zk.x + zm.x),  h * (zk.y - zm.y));
        float2 G1 = make_float2(h * (zk.y + zm.y), -h * (zk.x - zm.x));
        if (p == 0) {
            float2 z2 = A[SPAD(1024)];
            float2 G0n = make_float2(2.0f * z2.x, 0.0f);
            float2 G1n = make_float2(2.0f * z2.y, 0.0f);
            B[SPAD(0)] = make_float2(G0.x + G0n.x, G0.y + G0n.y);
            B[SPAD(1)] = make_float2(G0.x - G0n.x, G0.y - G0n.y);
            C[SPAD(0)] = make_float2(G1.x + G1n.x, G1.y + G1n.y);
            C[SPAD(1)] = make_float2(G1.x - G1n.x, G1.y - G1n.y);
        } else {
            float2 wc = tw[p]; wc.y = -wc.y;
            B[SPAD(2 * p)]     = G0;
            B[SPAD(2 * p + 1)] = cmul(wc, G0);
            C[SPAD(2 * p)]     = G1;
            C[SPAD(2 * p + 1)] = cmul(wc, G1);
        }
    }
    __syncthreads();

    ifft_tail(B, A, tw, tid);                  // analytic ch0 in A
    unsigned* __restrict__ d0 = g_theta + (size_t)ch0 * S_LEN;
    for (int i = tid; i < S_LEN; i += FFT_THREADS) {
        float2 a = A[SPAD(i)];
        d0[i] = diamond_u32(a.x, a.y);
    }
    __syncthreads();

    ifft_tail(C, B, tw, tid);                  // analytic ch1 in B
    unsigned* __restrict__ d1 = d0 + S_LEN;
    for (int i = tid; i < S_LEN; i += FFT_THREADS) {
        float2 a = B[SPAD(i)];
        d1[i] = diamond_u32(a.x, a.y);
    }
}

// ---------------------------------------------------------------------------
// Kernel 2: pairwise sign counting + fused finalize.
// bit = (ui - uj) >> 31  (UNSIGNED subtract: defined mod-2^32 wrap == mod-2pi)
// counts sin<0 events. 256-thread blocks, grid=512 => single co-resident wave
// (4 blocks/SM x 148 = 592 slots). Named scalar accumulators, constant-LUT
// tile decode, packed-byte HW REDUX reduction (fields <= 64, carry-free),
// 16-lane spread atomicAdd. Last block writes the output matrix.
// ---------------------------------------------------------------------------
__global__ __launch_bounds__(PLI_THREADS, 4)
void pli_kernel(float* __restrict__ out) {
    __shared__ unsigned sth[NCH * CHUNK];             // 16 KB
    __shared__ int is_last;
    const int sc  = blockIdx.x;                       // 0..NSC-1
    const int b   = blockIdx.y;                       // 0..NB-1
    const int tid = threadIdx.x;

    // stage CHUNK samples of all 64 channels (uint4 vectorized)
    const uint4* gsrc = reinterpret_cast<const uint4*>(g_theta);
    uint4* ssh = reinterpret_cast<uint4*>(sth);
    #pragma unroll
    for (int k = tid; k < NCH * (CHUNK / 4); k += PLI_THREADS) {
        int c  = k >> 4;                    // CHUNK/4 = 16 uint4 per channel
        int sp = k & 15;
        size_t gi = (((size_t)(b * NCH + c)) * S_LEN + (size_t)sc * CHUNK) / 4 + sp;
        ssh[k] = gsrc[gi];
    }
    __syncthreads();

    const int warp = tid >> 5;
    const int lane = tid & 31;

    for (int t = warp; t < 136; t += NWARPS) {
        const int tc = (int)c_tile[t];
        const int ti = tc >> 4;
        const int tj = tc & 15;

        const unsigned* rowi = sth + (ti * 4) * CHUNK + lane;
        const unsigned* rowj = sth + (tj * 4) * CHUNK + lane;

        unsigned a00 = 0, a01 = 0, a02 = 0, a03 = 0;
        unsigned a10 = 0, a11 = 0, a12 = 0, a13 = 0;
        unsigned a20 = 0, a21 = 0, a22 = 0, a23 = 0;
        unsigned a30 = 0, a31 = 0, a32 = 0, a33 = 0;

        #pragma unroll
        for (int it = 0; it < CHUNK / 32; it++) {
            const int s = it * 32;
            unsigned i0 = rowi[0 * CHUNK + s];
            unsigned i1 = rowi[1 * CHUNK + s];
            unsigned i2 = rowi[2 * CHUNK + s];
            unsigned i3 = rowi[3 * CHUNK + s];
            unsigned j0 = rowj[0 * CHUNK + s];
            unsigned j1 = rowj[1 * CHUNK + s];
            unsigned j2 = rowj[2 * CHUNK + s];
            unsigned j3 = rowj[3 * CHUNK + s];

            a00 += (i0 - j0) >> 31;  a01 += (i0 - j1) >> 31;
            a02 += (i0 - j2) >> 31;  a03 += (i0 - j3) >> 31;
            a10 += (i1 - j0) >> 31;  a11 += (i1 - j1) >> 31;
            a12 += (i1 - j2) >> 31;  a13 += (i1 - j3) >> 31;
            a20 += (i2 - j0) >> 31;  a21 += (i2 - j1) >> 31;
            a22 += (i2 - j2) >> 31;  a23 += (i2 - j3) >> 31;
            a30 += (i3 - j0) >> 31;  a31 += (i3 - j1) >> 31;
            a32 += (i3 - j2) >> 31;  a33 += (i3 - j3) >> 31;
        }

        // pack rows into bytes (per-lane counts <= 2, post-REDUX <= 64)
        unsigned P0 = a00 | (a01 << 8) | (a02 << 16) | (a03 << 24);
        unsigned P1 = a10 | (a11 << 8) | (a12 << 16) | (a13 << 24);
        unsigned P2 = a20 | (a21 << 8) | (a22 << 16) | (a23 << 24);
        unsigned P3 = a30 | (a31 << 8) | (a32 << 16) | (a33 << 24);

        // HW warp reduction (REDUX on sm_10x) — carry-free on byte fields
        P0 = __reduce_add_sync(0xffffffffu, P0);
        P1 = __reduce_add_sync(0xffffffffu, P1);
        P2 = __reduce_add_sync(0xffffffffu, P2);
        P3 = __reduce_add_sync(0xffffffffu, P3);

        if (lane < 16) {
            unsigned Plo = (lane & 4) ? P1 : P0;
            unsigned Phi = (lane & 4) ? P3 : P2;
            unsigned Pr  = (lane & 8) ? Phi : Plo;
            unsigned val = (Pr >> ((lane & 3) * 8)) & 0xFFu;
            int row = ti * 4 + ((lane >> 2) & 3);
            int col = tj * 4 + (lane & 3);
            atomicAdd(&g_cnt[(b * NCH + row) * NCH + col], (int)val);
        }
    }

    // ---- fused finalize: last block to finish writes the output ----
    __syncthreads();
    if (tid == 0) {
        __threadfence();
        int done = atomicAdd(&g_done, 1);
        is_last = (done == N_PLI_BLOCKS - 1);
    }
    __syncthreads();
    if (is_last) {
        __threadfence();
        for (int idx = tid; idx < NB * NCH * NCH; idx += PLI_THREADS) {
            int bb = idx >> 12;
            int i  = (idx >> 6) & 63;
            int j  = idx & 63;
            float v = 0.0f;
            if (i != j) {
                int n = (i < j) ? g_cnt[(bb * NCH + i) * NCH + j]
                                : g_cnt[(bb * NCH + j) * NCH + i];
                v = fabsf((float)S_LEN - 2.0f * (float)n) * (1.0f / (float)S_LEN);
            }
            out[idx] = v;
        }
    }
}

// ---------------------------------------------------------------------------
extern "C" void kernel_launch(void* const* d_in, const int* in_sizes, int n_in,
                              void* d_out, int out_size) {
    const float* x = (const float*)d_in[0];
    float* out = (float*)d_out;
    (void)in_sizes; (void)n_in; (void)out_size;

    const int fft_smem = (3 * FFT_PADDED + 1024) * (int)sizeof(float2);
    cudaFuncSetAttribute(hilbert_kernel,
                         cudaFuncAttributeMaxDynamicSharedMemorySize, fft_smem);

    hilbert_kernel<<<NB * NCH / 2, FFT_THREADS, fft_smem>>>(x);
    pli_kernel<<<dim3(NSC, NB), PLI_THREADS>>>(out);
}

// round 8
// speedup vs baseline: 1.0059x; 1.0059x over previous
#include <cuda_runtime.h>

#define S_LEN   2048
#define NCH     64
#define NB      16
#define CHUNK   128
#define NSC     (S_LEN / CHUNK)        // 16 sample-chunks
#define TSPLIT  3                      // tile-groups per (sc,b)
#define PLI_THREADS 256
#define NWARPS  (PLI_THREADS / 32)     // 8
#define FFT_THREADS 512
#define N_PLI_BLOCKS (NSC * TSPLIT * NB)   // 768 (single wave @6/SM)

// Scratch (static __device__ allocation — allowed by harness rules)
__device__ unsigned g_theta[NB * NCH * S_LEN];    // 8 MB quantized phase
__device__ int      g_cnt[NB * NCH * NCH];        // 256 KB counters
__device__ int      g_done;                       // finalize gate

// 136 upper-triangle 4x4-tile coords, packed (ti<<4)|tj
__constant__ unsigned char c_tile[136] = {
 0x00,0x01,0x02,0x03,0x04,0x05,0x06,0x07,0x08,0x09,0x0A,0x0B,0x0C,0x0D,0x0E,0x0F,
 0x11,0x12,0x13,0x14,0x15,0x16,0x17,0x18,0x19,0x1A,0x1B,0x1C,0x1D,0x1E,0x1F,
 0x22,0x23,0x24,0x25,0x26,0x27,0x28,0x29,0x2A,0x2B,0x2C,0x2D,0x2E,0x2F,
 0x33,0x34,0x35,0x36,0x37,0x38,0x39,0x3A,0x3B,0x3C,0x3D,0x3E,0x3F,
 0x44,0x45,0x46,0x47,0x48,0x49,0x4A,0x4B,0x4C,0x4D,0x4E,0x4F,
 0x55,0x56,0x57,0x58,0x59,0x5A,0x5B,0x5C,0x5D,0x5E,0x5F,
 0x66,0x67,0x68,0x69,0x6A,0x6B,0x6C,0x6D,0x6E,0x6F,
 0x77,0x78,0x79,0x7A,0x7B,0x7C,0x7D,0x7E,0x7F,
 0x88,0x89,0x8A,0x8B,0x8C,0x8D,0x8E,0x8F,
 0x99,0x9A,0x9B,0x9C,0x9D,0x9E,0x9F,
 0xAA,0xAB,0xAC,0xAD,0xAE,0xAF,
 0xBB,0xBC,0xBD,0xBE,0xBF,
 0xCC,0xCD,0xCE,0xCF,
 0xDD,0xDE,0xDF,
 0xEE,0xEF,
 0xFF };

// tile-group boundaries for the 3-way split
__constant__ int c_tgrp[TSPLIT + 1] = {0, 46, 91, 136};

// shared-memory index padding for the FFT stages
__device__ __forceinline__ int SPAD(int i) { return i + (i >> 3); }
#define FFT_PADDED 2304

// ---------------------------------------------------------------------------
// Radix-4 Stockham autosort FFT (N = 2048 = 2 * 4^5), DIF, natural order.
// ---------------------------------------------------------------------------
__device__ __forceinline__ float2 cmul(float2 a, float2 b) {
    return make_float2(fmaf(a.x, b.x, -a.y * b.y),
                       fmaf(a.x, b.y,  a.y * b.x));
}

__device__ __forceinline__ void stage_r2_fwd(const float2* __restrict__ src,
                                             float2* __restrict__ dst,
                                             const float2* __restrict__ tw,
                                             int tid) {
    for (int p = tid; p < 1024; p += FFT_THREADS) {
        float2 w = tw[p];
        float2 a = src[SPAD(p)];
        float2 b = src[SPAD(p + 1024)];
        dst[SPAD(2 * p)]     = make_float2(a.x + b.x, a.y + b.y);
        dst[SPAD(2 * p + 1)] = cmul(w, make_float2(a.x - b.x, a.y - b.y));
    }
}

template<int L, int LOG2M, bool INV>
__device__ __forceinline__ void stage_r4(const float2* __restrict__ src,
                                         float2* __restrict__ dst,
                                         const float2* __restrict__ tw,
                                         int tid) {
    constexpr int M   = 1 << LOG2M;
    constexpr int TWS = 512 / L;
    for (int t = tid; t < 512; t += FFT_THREADS) {
        const int p = t >> LOG2M;
        const int q = t & (M - 1);
        const int ib = q + M * p;
        float2 a = src[SPAD(ib)];
        float2 b = src[SPAD(ib + M * L)];
        float2 c = src[SPAD(ib + 2 * M * L)];
        float2 d = src[SPAD(ib + 3 * M * L)];

        float2 w1 = tw[p * TWS];
        float2 w2 = tw[2 * p * TWS];
        if (INV) { w1.y = -w1.y; w2.y = -w2.y; }
        float2 w3 = cmul(w1, w2);

        float2 t0 = make_float2(a.x + c.x, a.y + c.y);
        float2 t1 = make_float2(a.x - c.x, a.y - c.y);
        float2 t2 = make_float2(b.x + d.x, b.y + d.y);
        float2 e  = make_float2(b.x - d.x, b.y - d.y);
        float2 t3 = INV ? make_float2(-e.y,  e.x)
                        : make_float2( e.y, -e.x);

        const int ob = q + 4 * M * p;
        dst[SPAD(ob)]         = make_float2(t0.x + t2.x, t0.y + t2.y);
        dst[SPAD(ob + M)]     = cmul(w1, make_float2(t1.x + t3.x, t1.y + t3.y));
        dst[SPAD(ob + 2 * M)] = cmul(w2, make_float2(t0.x - t2.x, t0.y - t2.y));
        dst[SPAD(ob + 3 * M)] = cmul(w3, make_float2(t1.x - t3.x, t1.y - t3.y));
    }
}

// 5 inverse radix-4 stages (after the fused stage-1). Result lands in Y.
// Ends with __syncthreads(), so both buffers are quiescent on return.
__device__ __forceinline__ void ifft_tail(float2* __restrict__ X,
                                          float2* __restrict__ Y,
                                          const float2* __restrict__ tw,
                                          int tid) {
    stage_r4<256, 1, true>(X, Y, tw, tid);  __syncthreads();
    stage_r4< 64, 3, true>(Y, X, tw, tid);  __syncthreads();
    stage_r4< 16, 5, true>(X, Y, tw, tid);  __syncthreads();
    stage_r4<  4, 7, true>(Y, X, tw, tid);  __syncthreads();
    stage_r4<  1, 9, true>(X, Y, tw, tid);  __syncthreads();
}

// Diamond angle, quantized so a half-turn == 2^31 exactly (mod 2^32).
// Monotone map of atan2(y,x); wrapped-difference sign tests are invariant
// under any monotone circular reparameterization with exact antipode offset.
__device__ __forceinline__ unsigned diamond_u32(float x, float y) {
    float r = __fdividef(y, fabsf(x) + fabsf(y));     // [-1,1]
    float d;
    if (x >= 0.0f) d = r;
    else           d = (y >= 0.0f) ? (2.0f - r) : (-2.0f - r);
    return (unsigned)__float2int_rn(d * 1073741824.0f);   // * 2^30
}

// Unpack + Hilbert filter + fused degenerate inverse stage-1 for index p.
// Writes channel-0 stage-1 outputs into B; RETURNS channel-1 stage-1 outputs
// (c0 -> slot 2p, c1 -> slot 2p+1) for a register stash (saves the C buffer).
__device__ __forceinline__ void unpack_stage1(const float2* __restrict__ A,
                                              float2* __restrict__ B,
                                              const float2* __restrict__ tw,
                                              int p, float2& c0, float2& c1) {
    float2 zk = A[SPAD(p)];
    float2 zm = A[SPAD((S_LEN - p) & (S_LEN - 1))];
    float  h  = (p == 0) ? 1.0f : 2.0f;
    float2 G0 = make_float2(h * (zk.x + zm.x),  h * (zk.y - zm.y));
    float2 G1 = make_float2(h * (zk.y + zm.y), -h * (zk.x - zm.x));
    if (p == 0) {
        float2 z2 = A[SPAD(1024)];          // G0[1024]=2*z2.x, G1[1024]=2*z2.y
        B[SPAD(0)] = make_float2(G0.x + 2.0f * z2.x, G0.y);
        B[SPAD(1)] = make_float2(G0.x - 2.0f * z2.x, G0.y);
        c0 = make_float2(G1.x + 2.0f * z2.y, G1.y);
        c1 = make_float2(G1.x - 2.0f * z2.y, G1.y);
    } else {
        float2 wc = tw[p]; wc.y = -wc.y;
        B[SPAD(2 * p)]     = G0;
        B[SPAD(2 * p + 1)] = cmul(wc, G0);
        c0 = G1;
        c1 = cmul(wc, G1);
    }
}

// ---------------------------------------------------------------------------
// Kernel 1: Hilbert analytic signal -> quantized phase, 2 channels per block.
// Two smem buffers + twiddles only (44 KB -> 4 blocks/SM -> 512 blocks =
// single wave); channel-1 stage-1 spectrum lives in registers between chains.
// Also zeroes g_cnt / g_done for the pli pass (stream-ordered before it).
// ---------------------------------------------------------------------------
__global__ __launch_bounds__(FFT_THREADS)
void hilbert_kernel(const float* __restrict__ x) {
    extern __shared__ float2 smem[];
    float2* A  = smem;                          // FFT_PADDED
    float2* B  = smem + FFT_PADDED;             // FFT_PADDED
    float2* tw = smem + 2 * FFT_PADDED;         // 1024

    const int tid = threadIdx.x;
    const int blk = blockIdx.x;                 // 0..511
    const int ch0 = 2 * blk;

    if (tid < 128) g_cnt[blk * 128 + tid] = 0;
    if (blk == 0 && tid == 0) g_done = 0;

    const float* __restrict__ x0 = x + (size_t)ch0 * S_LEN;
    const float* __restrict__ x1 = x0 + S_LEN;

    // precise twiddles (error margin: rel_err tolerance is tight)
    for (int k = tid; k < 1024; k += FFT_THREADS) {
        float sn, cs;
        sincosf((-6.283185307179586f / 2048.0f) * (float)k, &sn, &cs);
        tw[k] = make_float2(cs, sn);
    }
    for (int i = tid; i < S_LEN; i += FFT_THREADS)
        A[SPAD(i)] = make_float2(x0[i], x1[i]);
    __syncthreads();

    // forward FFT: result in A (natural order)
    stage_r2_fwd(A, B, tw, tid);               __syncthreads();
    stage_r4<256, 1, false>(B, A, tw, tid);    __syncthreads();
    stage_r4< 64, 3, false>(A, B, tw, tid);    __syncthreads();
    stage_r4< 16, 5, false>(B, A, tw, tid);    __syncthreads();
    stage_r4<  4, 7, false>(A, B, tw, tid);    __syncthreads();
    stage_r4<  1, 9, false>(B, A, tw, tid);    __syncthreads();

    // unpack/filter/stage-1: ch0 -> B, ch1 stage-1 -> registers
    float2 c0a, c0b, c1a, c1b;
    unpack_stage1(A, B, tw, tid,       c0a, c0b);
    unpack_stage1(A, B, tw, tid + 512, c1a, c1b);
    __syncthreads();

    // chain 0: B -> ... -> A holds analytic ch0
    ifft_tail(B, A, tw, tid);
    unsigned* __restrict__ d0 = g_theta + (size_t)ch0 * S_LEN;
    for (int i = tid; i < S_LEN; i += FFT_THREADS) {
        float2 a = A[SPAD(i)];
        d0[i] = diamond_u32(a.x, a.y);
    }
    // refill B with ch1 stage-1 from the register stash
    B[SPAD(2 * tid)]            = c0a;
    B[SPAD(2 * tid + 1)]        = c0b;
    B[SPAD(2 * (tid + 512))]     = c1a;
    B[SPAD(2 * (tid + 512) + 1)] = c1b;
    __syncthreads();   // A reads done + B writes visible

    // chain 1: B -> ... -> A holds analytic ch1
    ifft_tail(B, A, tw, tid);
    unsigned* __restrict__ d1 = d0 + S_LEN;
    for (int i = tid; i < S_LEN; i += FFT_THREADS) {
        float2 a = A[SPAD(i)];
        d1[i] = diamond_u32(a.x, a.y);
    }
}

// ---------------------------------------------------------------------------
// Kernel 2: pairwise sign counting + fused finalize.
// bit = (ui - uj) >> 31  (UNSIGNED subtract: defined mod-2^32 wrap == mod-2pi)
// counts sin<0 events. CHUNK=128 keeps per-tile-visit overhead amortized
// (R6 structure); 136 tiles split 3-ways across blocks -> grid 768 of
// 256 threads, 6 blocks/SM resident = single full wave at ~65% occupancy.
// Named scalar accumulators, LUT tile decode, packed-byte HW REDUX
// (per-lane counts <= 4, post-reduce <= 128, carry-free), 16-lane REDG.
// ---------------------------------------------------------------------------
__global__ __launch_bounds__(PLI_THREADS, 6)
void pli_kernel(float* __restrict__ out) {
    __shared__ unsigned sth[NCH * CHUNK];             // 32 KB
    __shared__ int is_last;
    const int bx  = blockIdx.x;                       // 0 .. NSC*TSPLIT-1
    const int sc  = bx / TSPLIT;
    const int tg  = bx - sc * TSPLIT;
    const int b   = blockIdx.y;
    const int tid = threadIdx.x;

    // stage CHUNK samples of all 64 channels (uint4 vectorized)
    const uint4* gsrc = reinterpret_cast<const uint4*>(g_theta);
    uint4* ssh = reinterpret_cast<uint4*>(sth);
    #pragma unroll
    for (int k = tid; k < NCH * (CHUNK / 4); k += PLI_THREADS) {
        int c  = k >> 5;                    // CHUNK/4 = 32 uint4 per channel
        int sp = k & 31;
        size_t gi = (((size_t)(b * NCH + c)) * S_LEN + (size_t)sc * CHUNK) / 4 + sp;
        ssh[k] = gsrc[gi];
    }
    __syncthreads();

    const int warp = tid >> 5;
    const int lane = tid & 31;
    const int tlo  = c_tgrp[tg];
    const int thi  = c_tgrp[tg + 1];

    for (int t = tlo + warp; t < thi; t += NWARPS) {
        const int tc = (int)c_tile[t];
        const int ti = tc >> 4;
        const int tj = tc & 15;

        const unsigned* rowi = sth + (ti * 4) * CHUNK + lane;
        const unsigned* rowj = sth + (tj * 4) * CHUNK + lane;

        unsigned a00 = 0, a01 = 0, a02 = 0, a03 = 0;
        unsigned a10 = 0, a11 = 0, a12 = 0, a13 = 0;
        unsigned a20 = 0, a21 = 0, a22 = 0, a23 = 0;
        unsigned a30 = 0, a31 = 0, a32 = 0, a33 = 0;

        #pragma unroll
        for (int it = 0; it < CHUNK / 32; it++) {
            const int s = it * 32;
            unsigned i0 = rowi[0 * CHUNK + s];
            unsigned i1 = rowi[1 * CHUNK + s];
            unsigned i2 = rowi[2 * CHUNK + s];
            unsigned i3 = rowi[3 * CHUNK + s];
            unsigned j0 = rowj[0 * CHUNK + s];
            unsigned j1 = rowj[1 * CHUNK + s];
            unsigned j2 = rowj[2 * CHUNK + s];
            unsigned j3 = rowj[3 * CHUNK + s];

            a00 += (i0 - j0) >> 31;  a01 += (i0 - j1) >> 31;
            a02 += (i0 - j2) >> 31;  a03 += (i0 - j3) >> 31;
            a10 += (i1 - j0) >> 31;  a11 += (i1 - j1) >> 31;
            a12 += (i1 - j2) >> 31;  a13 += (i1 - j3) >> 31;
            a20 += (i2 - j0) >> 31;  a21 += (i2 - j1) >> 31;
            a22 += (i2 - j2) >> 31;  a23 += (i2 - j3) >> 31;
            a30 += (i3 - j0) >> 31;  a31 += (i3 - j1) >> 31;
            a32 += (i3 - j2) >> 31;  a33 += (i3 - j3) >> 31;
        }

        // pack rows into bytes (per-lane counts <= 4, post-REDUX <= 128)
        unsigned P0 = a00 | (a01 << 8) | (a02 << 16) | (a03 << 24);
        unsigned P1 = a10 | (a11 << 8) | (a12 << 16) | (a13 << 24);
        unsigned P2 = a20 | (a21 << 8) | (a22 << 16) | (a23 << 24);
        unsigned P3 = a30 | (a31 << 8) | (a32 << 16) | (a33 << 24);

        // HW warp reduction (REDUX) — carry-free on byte fields
        P0 = __reduce_add_sync(0xffffffffu, P0);
        P1 = __reduce_add_sync(0xffffffffu, P1);
        P2 = __reduce_add_sync(0xffffffffu, P2);
        P3 = __reduce_add_sync(0xffffffffu, P3);

        if (lane < 16) {
            unsigned Plo = (lane & 4) ? P1 : P0;
            unsigned Phi = (lane & 4) ? P3 : P2;
            unsigned Pr  = (lane & 8) ? Phi : Plo;
            unsigned val = (Pr >> ((lane & 3) * 8)) & 0xFFu;
            int row = ti * 4 + ((lane >> 2) & 3);
            int col = tj * 4 + (lane & 3);
            atomicAdd(&g_cnt[(b * NCH + row) * NCH + col], (int)val);
        }
    }

    // ---- fused finalize: last block to finish writes the output ----
    __syncthreads();
    if (tid == 0) {
        __threadfence();
        int done = atomicAdd(&g_done, 1);
        is_last = (done == N_PLI_BLOCKS - 1);
    }
    __syncthreads();
    if (is_last) {
        __threadfence();
        for (int idx = tid; idx < NB * NCH * NCH; idx += PLI_THREADS) {
            int bb = idx >> 12;
            int i  = (idx >> 6) & 63;
            int j  = idx & 63;
            float v = 0.0f;
            if (i != j) {
                int n = (i < j) ? g_cnt[(bb * NCH + i) * NCH + j]
                                : g_cnt[(bb * NCH + j) * NCH + i];
                v = fabsf((float)S_LEN - 2.0f * (float)n) * (1.0f / (float)S_LEN);
            }
            out[idx] = v;
        }
    }
}

// ---------------------------------------------------------------------------
extern "C" void kernel_launch(void* const* d_in, const int* in_sizes, int n_in,
                              void* d_out, int out_size) {
    const float* x = (const float*)d_in[0];
    float* out = (float*)d_out;
    (void)in_sizes; (void)n_in; (void)out_size;

    const int fft_smem = (2 * FFT_PADDED + 1024) * (int)sizeof(float2); // 45056
    cudaFuncSetAttribute(hilbert_kernel,
                         cudaFuncAttributeMaxDynamicSharedMemorySize, fft_smem);

    hilbert_kernel<<<NB * NCH / 2, FFT_THREADS, fft_smem>>>(x);
    pli_kernel<<<dim3(NSC * TSPLIT, NB), PLI_THREADS>>>(out);
}

// round 9
// speedup vs baseline: 1.1124x; 1.1059x over previous
#include <cuda_runtime.h>

#define S_LEN   2048
#define NCH     64
#define NB      16
#define CHUNK   128
#define NSC     (S_LEN / CHUNK)        // 16 sample-chunks
#define PLI_THREADS 512
#define NWARPS  (PLI_THREADS / 32)     // 16
#define FFT_THREADS 512
#define N_PLI_BLOCKS (NSC * NB)        // 256

// Scratch (static __device__ allocation — allowed by harness rules)
__device__ float2 g_analytic[NB * NCH * S_LEN];   // 16 MB analytic signal
__device__ int    g_cnt[NB * NCH * NCH];          // 256 KB counters
__device__ int    g_done;                         // finalize gate

// 136 upper-triangle 4x4-tile coords, packed (ti<<4)|tj
__constant__ unsigned char c_tile[136] = {
 0x00,0x01,0x02,0x03,0x04,0x05,0x06,0x07,0x08,0x09,0x0A,0x0B,0x0C,0x0D,0x0E,0x0F,
 0x11,0x12,0x13,0x14,0x15,0x16,0x17,0x18,0x19,0x1A,0x1B,0x1C,0x1D,0x1E,0x1F,
 0x22,0x23,0x24,0x25,0x26,0x27,0x28,0x29,0x2A,0x2B,0x2C,0x2D,0x2E,0x2F,
 0x33,0x34,0x35,0x36,0x37,0x38,0x39,0x3A,0x3B,0x3C,0x3D,0x3E,0x3F,
 0x44,0x45,0x46,0x47,0x48,0x49,0x4A,0x4B,0x4C,0x4D,0x4E,0x4F,
 0x55,0x56,0x57,0x58,0x59,0x5A,0x5B,0x5C,0x5D,0x5E,0x5F,
 0x66,0x67,0x68,0x69,0x6A,0x6B,0x6C,0x6D,0x6E,0x6F,
 0x77,0x78,0x79,0x7A,0x7B,0x7C,0x7D,0x7E,0x7F,
 0x88,0x89,0x8A,0x8B,0x8C,0x8D,0x8E,0x8F,
 0x99,0x9A,0x9B,0x9C,0x9D,0x9E,0x9F,
 0xAA,0xAB,0xAC,0xAD,0xAE,0xAF,
 0xBB,0xBC,0xBD,0xBE,0xBF,
 0xCC,0xCD,0xCE,0xCF,
 0xDD,0xDE,0xDF,
 0xEE,0xEF,
 0xFF };

// shared-memory index padding for the FFT stages
__device__ __forceinline__ int SPAD(int i) { return i + (i >> 3); }
#define FFT_PADDED 2304

// ---------------------------------------------------------------------------
// Radix-4 Stockham autosort FFT (N = 2048 = 2 * 4^5), DIF, natural order.
// ---------------------------------------------------------------------------
__device__ __forceinline__ float2 cmul(float2 a, float2 b) {
    return make_float2(fmaf(a.x, b.x, -a.y * b.y),
                       fmaf(a.x, b.y,  a.y * b.x));
}

__device__ __forceinline__ void stage_r2_fwd(const float2* __restrict__ src,
                                             float2* __restrict__ dst,
                                             const float2* __restrict__ tw,
                                             int tid) {
    for (int p = tid; p < 1024; p += FFT_THREADS) {
        float2 w = tw[p];
        float2 a = src[SPAD(p)];
        float2 b = src[SPAD(p + 1024)];
        dst[SPAD(2 * p)]     = make_float2(a.x + b.x, a.y + b.y);
        dst[SPAD(2 * p + 1)] = cmul(w, make_float2(a.x - b.x, a.y - b.y));
    }
}

template<int L, int LOG2M, bool INV>
__device__ __forceinline__ void stage_r4(const float2* __restrict__ src,
                                         float2* __restrict__ dst,
                                         const float2* __restrict__ tw,
                                         int tid) {
    constexpr int M   = 1 << LOG2M;
    constexpr int TWS = 512 / L;
    for (int t = tid; t < 512; t += FFT_THREADS) {
        const int p = t >> LOG2M;
        const int q = t & (M - 1);
        const int ib = q + M * p;
        float2 a = src[SPAD(ib)];
        float2 b = src[SPAD(ib + M * L)];
        float2 c = src[SPAD(ib + 2 * M * L)];
        float2 d = src[SPAD(ib + 3 * M * L)];

        float2 w1 = tw[p * TWS];
        float2 w2 = tw[2 * p * TWS];
        if (INV) { w1.y = -w1.y; w2.y = -w2.y; }
        float2 w3 = cmul(w1, w2);

        float2 t0 = make_float2(a.x + c.x, a.y + c.y);
        float2 t1 = make_float2(a.x - c.x, a.y - c.y);
        float2 t2 = make_float2(b.x + d.x, b.y + d.y);
        float2 e  = make_float2(b.x - d.x, b.y - d.y);
        float2 t3 = INV ? make_float2(-e.y,  e.x)
                        : make_float2( e.y, -e.x);

        const int ob = q + 4 * M * p;
        dst[SPAD(ob)]         = make_float2(t0.x + t2.x, t0.y + t2.y);
        dst[SPAD(ob + M)]     = cmul(w1, make_float2(t1.x + t3.x, t1.y + t3.y));
        dst[SPAD(ob + 2 * M)] = cmul(w2, make_float2(t0.x - t2.x, t0.y - t2.y));
        dst[SPAD(ob + 3 * M)] = cmul(w3, make_float2(t1.x - t3.x, t1.y - t3.y));
    }
}

// 5 inverse radix-4 stages (after the fused stage-1). Result lands in Y.
__device__ __forceinline__ void ifft_tail(float2* __restrict__ X,
                                          float2* __restrict__ Y,
                                          const float2* __restrict__ tw,
                                          int tid) {
    stage_r4<256, 1, true>(X, Y, tw, tid);  __syncthreads();
    stage_r4< 64, 3, true>(Y, X, tw, tid);  __syncthreads();
    stage_r4< 16, 5, true>(X, Y, tw, tid);  __syncthreads();
    stage_r4<  4, 7, true>(Y, X, tw, tid);  __syncthreads();
    stage_r4<  1, 9, true>(X, Y, tw, tid);  __syncthreads();
}

// Unpack + Hilbert filter + fused degenerate inverse stage-1 for index p.
// Writes channel-0 stage-1 outputs into B; RETURNS channel-1 stage-1 outputs
// (slots 2p, 2p+1) for a register stash (saves a third smem buffer).
__device__ __forceinline__ void unpack_stage1(const float2* __restrict__ A,
                                              float2* __restrict__ B,
                                              const float2* __restrict__ tw,
                                              int p, float2& c0, float2& c1) {
    float2 zk = A[SPAD(p)];
    float2 zm = A[SPAD((S_LEN - p) & (S_LEN - 1))];
    float  h  = (p == 0) ? 1.0f : 2.0f;
    float2 G0 = make_float2(h * (zk.x + zm.x),  h * (zk.y - zm.y));
    float2 G1 = make_float2(h * (zk.y + zm.y), -h * (zk.x - zm.x));
    if (p == 0) {
        float2 z2 = A[SPAD(1024)];          // G0[1024]=2*z2.x, G1[1024]=2*z2.y
        B[SPAD(0)] = make_float2(G0.x + 2.0f * z2.x, G0.y);
        B[SPAD(1)] = make_float2(G0.x - 2.0f * z2.x, G0.y);
        c0 = make_float2(G1.x + 2.0f * z2.y, G1.y);
        c1 = make_float2(G1.x - 2.0f * z2.y, G1.y);
    } else {
        float2 wc = tw[p]; wc.y = -wc.y;
        B[SPAD(2 * p)]     = G0;
        B[SPAD(2 * p + 1)] = cmul(wc, G0);
        c0 = G1;
        c1 = cmul(wc, G1);
    }
}

// ---------------------------------------------------------------------------
// Kernel 1: Hilbert analytic signal, 2 channels per block, float2 output.
// Two smem buffers + twiddles (44 KB -> 4 blocks/SM -> 512 blocks = single
// wave); channel-1 stage-1 spectrum stashed in registers between chains.
// No angle function: pli uses the raw cross-product sign.
// Also zeroes g_cnt / g_done for the pli pass (stream-ordered before it).
// ---------------------------------------------------------------------------
__global__ __launch_bounds__(FFT_THREADS)
void hilbert_kernel(const float* __restrict__ x) {
    extern __shared__ float2 smem[];
    float2* A  = smem;                          // FFT_PADDED
    float2* B  = smem + FFT_PADDED;             // FFT_PADDED
    float2* tw = smem + 2 * FFT_PADDED;         // 1024

    const int tid = threadIdx.x;
    const int blk = blockIdx.x;                 // 0..511
    const int ch0 = 2 * blk;

    if (tid < 128) g_cnt[blk * 128 + tid] = 0;
    if (blk == 0 && tid == 0) g_done = 0;

    const float* __restrict__ x0 = x + (size_t)ch0 * S_LEN;
    const float* __restrict__ x1 = x0 + S_LEN;

    for (int k = tid; k < 1024; k += FFT_THREADS) {
        float sn, cs;
        sincosf((-6.283185307179586f / 2048.0f) * (float)k, &sn, &cs);
        tw[k] = make_float2(cs, sn);
    }
    for (int i = tid; i < S_LEN; i += FFT_THREADS)
        A[SPAD(i)] = make_float2(x0[i], x1[i]);
    __syncthreads();

    // forward FFT: result in A (natural order)
    stage_r2_fwd(A, B, tw, tid);               __syncthreads();
    stage_r4<256, 1, false>(B, A, tw, tid);    __syncthreads();
    stage_r4< 64, 3, false>(A, B, tw, tid);    __syncthreads();
    stage_r4< 16, 5, false>(B, A, tw, tid);    __syncthreads();
    stage_r4<  4, 7, false>(A, B, tw, tid);    __syncthreads();
    stage_r4<  1, 9, false>(B, A, tw, tid);    __syncthreads();

    // unpack/filter/stage-1: ch0 -> B, ch1 stage-1 -> registers
    float2 c0a, c0b, c1a, c1b;
    unpack_stage1(A, B, tw, tid,       c0a, c0b);
    unpack_stage1(A, B, tw, tid + 512, c1a, c1b);
    __syncthreads();

    // chain 0: analytic ch0 lands in A
    ifft_tail(B, A, tw, tid);
    float2* __restrict__ d0 = g_analytic + (size_t)ch0 * S_LEN;
    for (int i = tid; i < S_LEN; i += FFT_THREADS)
        d0[i] = A[SPAD(i)];
    // refill B with ch1 stage-1 from the register stash
    B[SPAD(2 * tid)]             = c0a;
    B[SPAD(2 * tid + 1)]         = c0b;
    B[SPAD(2 * (tid + 512))]     = c1a;
    B[SPAD(2 * (tid + 512) + 1)] = c1b;
    __syncthreads();

    // chain 1: analytic ch1 lands in A
    ifft_tail(B, A, tw, tid);
    float2* __restrict__ d1 = d0 + S_LEN;
    for (int i = tid; i < S_LEN; i += FFT_THREADS)
        d1[i] = A[SPAD(i)];
}

// ---------------------------------------------------------------------------
// Kernel 2: pairwise sign counting (PROVEN-FAST R2 inner loop) + fused
// finalize. sign(sin(ti - tj)) == sign(y_i*x_j - x_i*y_j): float cross
// (FMUL + FFMA), ONE ballot counts positives P, sumsign = 2P - S (exact
// zeros are measure-zero). 512 threads, 64 KB dynamic smem, grid 256.
// ---------------------------------------------------------------------------
__global__ __launch_bounds__(PLI_THREADS)
void pli_kernel(float* __restrict__ out) {
    extern __shared__ float2 sdata[];                 // [NCH][CHUNK], 64 KB
    __shared__ int is_last;
    const int sc  = blockIdx.x;
    const int b   = blockIdx.y;
    const int tid = threadIdx.x;

    // stage channels into smem with float4 (2 samples per load)
    const float4* gsrc = reinterpret_cast<const float4*>(g_analytic);
    float4* ssh = reinterpret_cast<float4*>(sdata);
    for (int k = tid; k < NCH * (CHUNK / 2); k += PLI_THREADS) {
        int c  = k / (CHUNK / 2);
        int sp = k - c * (CHUNK / 2);
        size_t gi = (((size_t)(b * NCH + c)) * S_LEN + (size_t)sc * CHUNK) / 2 + sp;
        ssh[c * (CHUNK / 2) + sp] = gsrc[gi];
    }
    __syncthreads();

    const int warp = tid >> 5;
    const int lane = tid & 31;

    for (int t = warp; t < 136; t += NWARPS) {
        const int tc = (int)c_tile[t];
        const int ti = tc >> 4;
        const int tj = tc & 15;

        const float2* rowi = sdata + (ti * 4) * CHUNK;
        const float2* rowj = sdata + (tj * 4) * CHUNK;

        int acc[16];
        #pragma unroll
        for (int q = 0; q < 16; q++) acc[q] = 0;

        #pragma unroll
        for (int it = 0; it < CHUNK / 32; it++) {
            int s = it * 32 + lane;
            float2 ai[4], aj[4];
            #pragma unroll
            for (int a = 0; a < 4; a++) ai[a] = rowi[a * CHUNK + s];
            #pragma unroll
            for (int a = 0; a < 4; a++) aj[a] = rowj[a * CHUNK + s];

            #pragma unroll
            for (int a = 0; a < 4; a++) {
                #pragma unroll
                for (int c2 = 0; c2 < 4; c2++) {
                    float p     = ai[a].x * aj[c2].y;
                    float cross = fmaf(ai[a].y, aj[c2].x, -p);
                    unsigned mp = __ballot_sync(0xffffffffu, cross > 0.0f);
                    acc[a * 4 + c2] += __popc(mp);
                }
            }
        }

        if (lane == 0) {
            #pragma unroll
            for (int a = 0; a < 4; a++)
                #pragma unroll
                for (int c2 = 0; c2 < 4; c2++)
                    atomicAdd(&g_cnt[(b * NCH + ti * 4 + a) * NCH + tj * 4 + c2],
                              acc[a * 4 + c2]);
        }
    }

    // ---- fused finalize: last block to finish writes the output ----
    __syncthreads();
    if (tid == 0) {
        __threadfence();
        int done = atomicAdd(&g_done, 1);
        is_last = (done == N_PLI_BLOCKS - 1);
    }
    __syncthreads();
    if (is_last) {
        __threadfence();
        for (int idx = tid; idx < NB * NCH * NCH; idx += PLI_THREADS) {
            int bb = idx >> 12;
            int i  = (idx >> 6) & 63;
            int j  = idx & 63;
            float v = 0.0f;
            if (i != j) {
                int p = (i < j) ? g_cnt[(bb * NCH + i) * NCH + j]
                                : g_cnt[(bb * NCH + j) * NCH + i];
                v = fabsf(2.0f * (float)p - (float)S_LEN) * (1.0f / (float)S_LEN);
            }
            out[idx] = v;
        }
    }
}

// ---------------------------------------------------------------------------
extern "C" void kernel_launch(void* const* d_in, const int* in_sizes, int n_in,
                              void* d_out, int out_size) {
    const float* x = (const float*)d_in[0];
    float* out = (float*)d_out;
    (void)in_sizes; (void)n_in; (void)out_size;

    const int fft_smem = (2 * FFT_PADDED + 1024) * (int)sizeof(float2); // 45056
    const int pli_smem = NCH * CHUNK * (int)sizeof(float2);             // 65536
    cudaFuncSetAttribute(hilbert_kernel,
                         cudaFuncAttributeMaxDynamicSharedMemorySize, fft_smem);
    cudaFuncSetAttribute(pli_kernel,
                         cudaFuncAttributeMaxDynamicSharedMemorySize, pli_smem);

    hilbert_kernel<<<NB * NCH / 2, FFT_THREADS, fft_smem>>>(x);
    pli_kernel<<<dim3(NSC, NB), PLI_THREADS, pli_smem>>>(out);
}

// round 10
// speedup vs baseline: 1.9097x; 1.7168x over previous
#include <cuda_runtime.h>

#define S_LEN   2048
#define NCH     64
#define NB      16
#define CHUNK   128
#define NSC     (S_LEN / CHUNK)        // 16 sample-chunks
#define PLI_THREADS 512
#define NWARPS  (PLI_THREADS / 32)
#define FFT_THREADS 256

// Scratch (static __device__ allocation — allowed by harness rules)
__device__ float2 g_analytic[NB * NCH * S_LEN];   // 16 MB
__device__ int    g_cnt[NB * NCH * NCH];          // 256 KB of int counters

// ---------------------------------------------------------------------------
// Kernel 0: zero the counters
// ---------------------------------------------------------------------------
__global__ void zero_cnt_kernel() {
    int idx = blockIdx.x * blockDim.x + threadIdx.x;
    if (idx < NB * NCH * NCH) g_cnt[idx] = 0;
}

// ---------------------------------------------------------------------------
// Radix-4 Stockham autosort FFT pieces (N = 2048 = 2 * 4^5).
// DIF formulation; natural-order in, natural-order out; ping-pong buffers.
// ---------------------------------------------------------------------------
__device__ __forceinline__ float2 cmul(float2 a, float2 b) {
    return make_float2(fmaf(a.x, b.x, -a.y * b.y),
                       fmaf(a.x, b.y,  a.y * b.x));
}

// radix-2 first stage (forward): l = 1024, m = 1
__device__ __forceinline__ void stage_r2_fwd(const float2* __restrict__ src,
                                             float2* __restrict__ dst,
                                             const float2* __restrict__ tw,
                                             int tid) {
    #pragma unroll 4
    for (int p = tid; p < 1024; p += FFT_THREADS) {
        float2 w = tw[p];                       // exp(-2*pi*i p/2048)
        float2 a = src[p];
        float2 b = src[p + 1024];
        dst[2 * p]     = make_float2(a.x + b.x, a.y + b.y);
        dst[2 * p + 1] = cmul(w, make_float2(a.x - b.x, a.y - b.y));
    }
}

// radix-4 stage: L * M * 4 == 2048
template<int L, int LOG2M, bool INV>
__device__ __forceinline__ void stage_r4(const float2* __restrict__ src,
                                         float2* __restrict__ dst,
                                         const float2* __restrict__ tw,
                                         int tid) {
    constexpr int M   = 1 << LOG2M;
    constexpr int TWS = 512 / L;                // twiddle stride
    #pragma unroll
    for (int t = tid; t < 512; t += FFT_THREADS) {
        const int p = t >> LOG2M;
        const int q = t & (M - 1);
        const int ib = q + M * p;               // == t
        float2 a = src[ib];
        float2 b = src[ib + M * L];
        float2 c = src[ib + 2 * M * L];
        float2 d = src[ib + 3 * M * L];

        float2 w1 = tw[p * TWS];                // exp(-2*pi*i p/(4L))
        float2 w2 = tw[2 * p * TWS];
        if (INV) { w1.y = -w1.y; w2.y = -w2.y; }
        float2 w3 = cmul(w1, w2);

        float2 t0 = make_float2(a.x + c.x, a.y + c.y);
        float2 t1 = make_float2(a.x - c.x, a.y - c.y);
        float2 t2 = make_float2(b.x + d.x, b.y + d.y);
        float2 e  = make_float2(b.x - d.x, b.y - d.y);
        float2 t3 = INV ? make_float2(-e.y,  e.x)
                        : make_float2( e.y, -e.x);

        const int ob = q + 4 * M * p;
        dst[ob]         = make_float2(t0.x + t2.x, t0.y + t2.y);
        dst[ob + M]     = cmul(w1, make_float2(t1.x + t3.x, t1.y + t3.y));
        dst[ob + 2 * M] = cmul(w2, make_float2(t0.x - t2.x, t0.y - t2.y));
        dst[ob + 3 * M] = cmul(w3, make_float2(t1.x - t3.x, t1.y - t3.y));
    }
}

// 5 inverse radix-4 stages (after the fused degenerate stage-1).
// X -> Y -> X -> Y -> X -> Y : result lands in Y.
__device__ __forceinline__ void ifft_tail(float2* __restrict__ X,
                                          float2* __restrict__ Y,
                                          const float2* __restrict__ tw,
                                          int tid) {
    stage_r4<256, 1, true>(X, Y, tw, tid);  __syncthreads();
    stage_r4< 64, 3, true>(Y, X, tw, tid);  __syncthreads();
    stage_r4< 16, 5, true>(X, Y, tw, tid);  __syncthreads();
    stage_r4<  4, 7, true>(Y, X, tw, tid);  __syncthreads();
    stage_r4<  1, 9, true>(X, Y, tw, tid);  __syncthreads();
}

// ---------------------------------------------------------------------------
// Kernel 1: Hilbert analytic signal, 2 channels per block (R2 recipe:
// 256 threads, 3 unpadded buffers, sincosf twiddles), with ONE change vs R2:
// the unpack + Hilbert filter is fused with the degenerate first inverse
// stage (spectrum zero for k > N/2), removing the zero-half write pass and
// one radix-2 stage per inverse chain. Scale factors (1/2, 1/N) dropped:
// PLI uses only signs of cross products.
// ---------------------------------------------------------------------------
__global__ __launch_bounds__(FFT_THREADS)
void hilbert_kernel(const float* __restrict__ x) {
    __shared__ float2 A   [S_LEN];
    __shared__ float2 B   [S_LEN];
    __shared__ float2 Cb  [S_LEN];
    __shared__ float2 tw  [S_LEN / 2];

    const int bc  = blockIdx.x;               // 0..511 (channel pair)
    const int tid = threadIdx.x;
    const int ch0 = 2 * bc;

    const float* __restrict__ x0 = x + (size_t)ch0 * S_LEN;
    const float* __restrict__ x1 = x0 + S_LEN;

    // twiddles: tw[k] = exp(-2*pi*i*k / S)
    for (int k = tid; k < S_LEN / 2; k += FFT_THREADS) {
        float ang = (-6.283185307179586f / (float)S_LEN) * (float)k;
        float sn, cs;
        sincosf(ang, &sn, &cs);
        tw[k] = make_float2(cs, sn);
    }
    // pack two real channels into one complex signal
    for (int i = tid; i < S_LEN; i += FFT_THREADS)
        A[i] = make_float2(x0[i], x1[i]);
    __syncthreads();

    // forward FFT: A -> B -> A -> B -> A -> B -> A (result in A, natural)
    stage_r2_fwd(A, B, tw, tid);               __syncthreads();
    stage_r4<256, 1, false>(B, A, tw, tid);    __syncthreads();
    stage_r4< 64, 3, false>(A, B, tw, tid);    __syncthreads();
    stage_r4< 16, 5, false>(B, A, tw, tid);    __syncthreads();
    stage_r4<  4, 7, false>(A, B, tw, tid);    __syncthreads();
    stage_r4<  1, 9, false>(B, A, tw, tid);    __syncthreads();

    // Unpack + Hilbert filter + fused degenerate inverse stage-1:
    //   G0[k] = h[k]*(Z[k] + conj(Z[N-k]))        (ch0 spectrum)
    //   G1[k] = h[k]*(-i)*(Z[k] - conj(Z[N-k]))   (ch1 spectrum)
    // Zero for k > N/2  =>  inverse stage-1 (radix-2) degenerates:
    //   p>=1 : dst[2p] = G[p], dst[2p+1] = conj(w_p)*G[p]
    //   p==0 : dst[0] = G[0]+G[1024], dst[1] = G[0]-G[1024]
    for (int p = tid; p < 1024; p += FFT_THREADS) {
        float2 zk = A[p];
        float2 zm = A[(S_LEN - p) & (S_LEN - 1)];
        float  h  = (p == 0) ? 1.0f : 2.0f;
        float2 G0 = make_float2(h * (zk.x + zm.x),  h * (zk.y - zm.y));
        float2 G1 = make_float2(h * (zk.y + zm.y), -h * (zk.x - zm.x));
        if (p == 0) {
            float2 z2 = A[1024];    // G0[1024] = 2*z2.x ; G1[1024] = 2*z2.y
            B [0] = make_float2(G0.x + 2.0f * z2.x, G0.y);
            B [1] = make_float2(G0.x - 2.0f * z2.x, G0.y);
            Cb[0] = make_float2(G1.x + 2.0f * z2.y, G1.y);
            Cb[1] = make_float2(G1.x - 2.0f * z2.y, G1.y);
        } else {
            float2 wc = tw[p]; wc.y = -wc.y;
            B [2 * p]     = G0;
            B [2 * p + 1] = cmul(wc, G0);
            Cb[2 * p]     = G1;
            Cb[2 * p + 1] = cmul(wc, G1);
        }
    }
    __syncthreads();

    // inverse chain 0 (B <-> A, result in A): analytic ch0
    ifft_tail(B, A, tw, tid);
    float2* __restrict__ d0 = g_analytic + (size_t)ch0 * S_LEN;
    for (int i = tid; i < S_LEN; i += FFT_THREADS)
        d0[i] = A[i];
    __syncthreads();

    // inverse chain 1 (Cb <-> B, result in B): analytic ch1
    ifft_tail(Cb, B, tw, tid);
    float2* __restrict__ d1 = d0 + S_LEN;
    for (int i = tid; i < S_LEN; i += FFT_THREADS)
        d1[i] = B[i];
}

// ---------------------------------------------------------------------------
// Kernel 2: pairwise sign counting (byte-identical to R2's proven kernel).
// sign(sin(ti - tj)) == sign(y_i*x_j - x_i*y_j); ballot+popc both signs.
// ---------------------------------------------------------------------------
__global__ __launch_bounds__(PLI_THREADS)
void pli_kernel() {
    extern __shared__ float2 sdata[];                 // [NCH][CHUNK]
    const int sc  = blockIdx.x;
    const int b   = blockIdx.y;
    const int tid = threadIdx.x;

    const float4* gsrc = reinterpret_cast<const float4*>(g_analytic);
    float4* ssh = reinterpret_cast<float4*>(sdata);
    for (int k = tid; k < NCH * (CHUNK / 2); k += PLI_THREADS) {
        int c  = k / (CHUNK / 2);
        int sp = k - c * (CHUNK / 2);
        size_t gi = (((size_t)(b * NCH + c)) * S_LEN + (size_t)sc * CHUNK) / 2 + sp;
        ssh[c * (CHUNK / 2) + sp] = gsrc[gi];
    }
    __syncthreads();

    const int warp = tid >> 5;
    const int lane = tid & 31;

    for (int t = warp; t < 136; t += NWARPS) {
        int ti = 0, rem = t;
        while (rem >= (16 - ti)) { rem -= (16 - ti); ti++; }
        int tj = ti + rem;

        const float2* rowi = sdata + (ti * 4) * CHUNK;
        const float2* rowj = sdata + (tj * 4) * CHUNK;

        int acc[16];
        #pragma unroll
        for (int q = 0; q < 16; q++) acc[q] = 0;

        #pragma unroll
        for (int it = 0; it < CHUNK / 32; it++) {
            int s = it * 32 + lane;
            float2 ai[4], aj[4];
            #pragma unroll
            for (int a = 0; a < 4; a++) ai[a] = rowi[a * CHUNK + s];
            #pragma unroll
            for (int a = 0; a < 4; a++) aj[a] = rowj[a * CHUNK + s];

            #pragma unroll
            for (int a = 0; a < 4; a++) {
                #pragma unroll
                for (int c2 = 0; c2 < 4; c2++) {
                    float p     = ai[a].x * aj[c2].y;
                    float cross = fmaf(ai[a].y, aj[c2].x, -p);
                    unsigned mp = __ballot_sync(0xffffffffu, cross > 0.0f);
                    acc[a * 4 + c2] += __popc(mp);
                }
            }
        }

        if (lane == 0) {
            #pragma unroll
            for (int a = 0; a < 4; a++) {
                #pragma unroll
                for (int c2 = 0; c2 < 4; c2++) {
                    atomicAdd(&g_cnt[(b * NCH + ti * 4 + a) * NCH + tj * 4 + c2],
                              acc[a * 4 + c2]);
                }
            }
        }
    }
}

// ---------------------------------------------------------------------------
// Kernel 3: finalize |2P - S|/S ; zero diagonal; mirror i>j.
// ---------------------------------------------------------------------------
__global__ void finalize_kernel(float* __restrict__ out) {
    int idx = blockIdx.x * blockDim.x + threadIdx.x;
    if (idx >= NB * NCH * NCH) return;
    int b = idx >> 12;
    int i = (idx >> 6) & 63;
    int j = idx & 63;
    float v = 0.0f;
    if (i != j) {
        int c = (i < j) ? g_cnt[(b * NCH + i) * NCH + j]
                        : g_cnt[(b * NCH + j) * NCH + i];
        v = fabsf(2.0f * (float)c - (float)S_LEN) * (1.0f / (float)S_LEN);
    }
    out[idx] = v;
}

// ---------------------------------------------------------------------------
extern "C" void kernel_launch(void* const* d_in, const int* in_sizes, int n_in,
                              void* d_out, int out_size) {
    const float* x = (const float*)d_in[0];
    float* out = (float*)d_out;
    (void)in_sizes; (void)n_in; (void)out_size;

    const int pli_smem = NCH * CHUNK * (int)sizeof(float2);   // 64 KB
    cudaFuncSetAttribute(pli_kernel,
                         cudaFuncAttributeMaxDynamicSharedMemorySize, pli_smem);

    zero_cnt_kernel<<<(NB * NCH * NCH + 1023) / 1024, 1024>>>();
    hilbert_kernel<<<NB * NCH / 2, FFT_THREADS>>>(x);
    pli_kernel<<<dim3(NSC, NB), PLI_THREADS, pli_smem>>>();
    finalize_kernel<<<(NB * NCH * NCH + 255) / 256, 256>>>(out);
}

// round 11
// speedup vs baseline: 2.2590x; 1.1829x over previous
#include <cuda_runtime.h>

#define S_LEN   2048
#define NCH     64
#define NB      16
#define CHUNK   128
#define NSC     (S_LEN / CHUNK)        // 16 sample-chunks
#define PLI_THREADS 512
#define NWARPS  (PLI_THREADS / 32)
#define FFT_THREADS 256

// Scratch (static __device__ allocation — allowed by harness rules)
__device__ float2 g_analytic[NB * NCH * S_LEN];   // 16 MB
__device__ int    g_cnt[NB * NCH * NCH];          // 256 KB of int counters

// ---------------------------------------------------------------------------
// Radix-4 Stockham autosort FFT pieces (N = 2048 = 2 * 4^5).
// DIF formulation; natural-order in, natural-order out; ping-pong buffers.
// ---------------------------------------------------------------------------
__device__ __forceinline__ float2 cmul(float2 a, float2 b) {
    return make_float2(fmaf(a.x, b.x, -a.y * b.y),
                       fmaf(a.x, b.y,  a.y * b.x));
}

// radix-2 first stage (forward): l = 1024, m = 1
__device__ __forceinline__ void stage_r2_fwd(const float2* __restrict__ src,
                                             float2* __restrict__ dst,
                                             const float2* __restrict__ tw,
                                             int tid) {
    #pragma unroll 4
    for (int p = tid; p < 1024; p += FFT_THREADS) {
        float2 w = tw[p];                       // exp(-2*pi*i p/2048)
        float2 a = src[p];
        float2 b = src[p + 1024];
        dst[2 * p]     = make_float2(a.x + b.x, a.y + b.y);
        dst[2 * p + 1] = cmul(w, make_float2(a.x - b.x, a.y - b.y));
    }
}

// radix-4 stage: L * M * 4 == 2048
template<int L, int LOG2M, bool INV>
__device__ __forceinline__ void stage_r4(const float2* __restrict__ src,
                                         float2* __restrict__ dst,
                                         const float2* __restrict__ tw,
                                         int tid) {
    constexpr int M   = 1 << LOG2M;
    constexpr int TWS = 512 / L;                // twiddle stride
    #pragma unroll
    for (int t = tid; t < 512; t += FFT_THREADS) {
        const int p = t >> LOG2M;
        const int q = t & (M - 1);
        const int ib = q + M * p;               // == t
        float2 a = src[ib];
        float2 b = src[ib + M * L];
        float2 c = src[ib + 2 * M * L];
        float2 d = src[ib + 3 * M * L];

        float2 w1 = tw[p * TWS];                // exp(-2*pi*i p/(4L))
        float2 w2 = tw[2 * p * TWS];
        if (INV) { w1.y = -w1.y; w2.y = -w2.y; }
        float2 w3 = cmul(w1, w2);

        float2 t0 = make_float2(a.x + c.x, a.y + c.y);
        float2 t1 = make_float2(a.x - c.x, a.y - c.y);
        float2 t2 = make_float2(b.x + d.x, b.y + d.y);
        float2 e  = make_float2(b.x - d.x, b.y - d.y);
        float2 t3 = INV ? make_float2(-e.y,  e.x)
                        : make_float2( e.y, -e.x);

        const int ob = q + 4 * M * p;
        dst[ob]         = make_float2(t0.x + t2.x, t0.y + t2.y);
        dst[ob + M]     = cmul(w1, make_float2(t1.x + t3.x, t1.y + t3.y));
        dst[ob + 2 * M] = cmul(w2, make_float2(t0.x - t2.x, t0.y - t2.y));
        dst[ob + 3 * M] = cmul(w3, make_float2(t1.x - t3.x, t1.y - t3.y));
    }
}

// 5 inverse radix-4 stages (after the fused degenerate stage-1).
// X -> Y -> X -> Y -> X -> Y : result lands in Y.
__device__ __forceinline__ void ifft_tail(float2* __restrict__ X,
                                          float2* __restrict__ Y,
                                          const float2* __restrict__ tw,
                                          int tid) {
    stage_r4<256, 1, true>(X, Y, tw, tid);  __syncthreads();
    stage_r4< 64, 3, true>(Y, X, tw, tid);  __syncthreads();
    stage_r4< 16, 5, true>(X, Y, tw, tid);  __syncthreads();
    stage_r4<  4, 7, true>(Y, X, tw, tid);  __syncthreads();
    stage_r4<  1, 9, true>(X, Y, tw, tid);  __syncthreads();
}

// ---------------------------------------------------------------------------
// Kernel 1: Hilbert analytic signal, 2 channels per block (anchor recipe:
// 256 threads, 3 unpadded static smem buffers, sincosf twiddles, fused
// degenerate inverse stage-1). Also zeroes g_cnt (512 blocks x 128 ints =
// 65536; stream order makes it visible to pli) — replaces the zero kernel.
// ---------------------------------------------------------------------------
__global__ __launch_bounds__(FFT_THREADS)
void hilbert_kernel(const float* __restrict__ x) {
    __shared__ float2 A   [S_LEN];
    __shared__ float2 B   [S_LEN];
    __shared__ float2 Cb  [S_LEN];
    __shared__ float2 tw  [S_LEN / 2];

    const int bc  = blockIdx.x;               // 0..511 (channel pair)
    const int tid = threadIdx.x;
    const int ch0 = 2 * bc;

    // fused counter zeroing (visible to pli via stream ordering)
    if (tid < 128) g_cnt[bc * 128 + tid] = 0;

    const float* __restrict__ x0 = x + (size_t)ch0 * S_LEN;
    const float* __restrict__ x1 = x0 + S_LEN;

    // twiddles: tw[k] = exp(-2*pi*i*k / S)
    for (int k = tid; k < S_LEN / 2; k += FFT_THREADS) {
        float ang = (-6.283185307179586f / (float)S_LEN) * (float)k;
        float sn, cs;
        sincosf(ang, &sn, &cs);
        tw[k] = make_float2(cs, sn);
    }
    // pack two real channels into one complex signal
    for (int i = tid; i < S_LEN; i += FFT_THREADS)
        A[i] = make_float2(x0[i], x1[i]);
    __syncthreads();

    // forward FFT: A -> B -> A -> B -> A -> B -> A (result in A, natural)
    stage_r2_fwd(A, B, tw, tid);               __syncthreads();
    stage_r4<256, 1, false>(B, A, tw, tid);    __syncthreads();
    stage_r4< 64, 3, false>(A, B, tw, tid);    __syncthreads();
    stage_r4< 16, 5, false>(B, A, tw, tid);    __syncthreads();
    stage_r4<  4, 7, false>(A, B, tw, tid);    __syncthreads();
    stage_r4<  1, 9, false>(B, A, tw, tid);    __syncthreads();

    // Unpack + Hilbert filter + fused degenerate inverse stage-1:
    //   G0[k] = h[k]*(Z[k] + conj(Z[N-k]))        (ch0 spectrum)
    //   G1[k] = h[k]*(-i)*(Z[k] - conj(Z[N-k]))   (ch1 spectrum)
    // Zero for k > N/2  =>  inverse stage-1 (radix-2) degenerates:
    //   p>=1 : dst[2p] = G[p], dst[2p+1] = conj(w_p)*G[p]
    //   p==0 : dst[0] = G[0]+G[1024], dst[1] = G[0]-G[1024]
    for (int p = tid; p < 1024; p += FFT_THREADS) {
        float2 zk = A[p];
        float2 zm = A[(S_LEN - p) & (S_LEN - 1)];
        float  h  = (p == 0) ? 1.0f : 2.0f;
        float2 G0 = make_float2(h * (zk.x + zm.x),  h * (zk.y - zm.y));
        float2 G1 = make_float2(h * (zk.y + zm.y), -h * (zk.x - zm.x));
        if (p == 0) {
            float2 z2 = A[1024];    // G0[1024] = 2*z2.x ; G1[1024] = 2*z2.y
            B [0] = make_float2(G0.x + 2.0f * z2.x, G0.y);
            B [1] = make_float2(G0.x - 2.0f * z2.x, G0.y);
            Cb[0] = make_float2(G1.x + 2.0f * z2.y, G1.y);
            Cb[1] = make_float2(G1.x - 2.0f * z2.y, G1.y);
        } else {
            float2 wc = tw[p]; wc.y = -wc.y;
            B [2 * p]     = G0;
            B [2 * p + 1] = cmul(wc, G0);
            Cb[2 * p]     = G1;
            Cb[2 * p + 1] = cmul(wc, G1);
        }
    }
    __syncthreads();

    // inverse chain 0 (B <-> A, result in A): analytic ch0
    ifft_tail(B, A, tw, tid);
    float2* __restrict__ d0 = g_analytic + (size_t)ch0 * S_LEN;
    for (int i = tid; i < S_LEN; i += FFT_THREADS)
        d0[i] = A[i];
    __syncthreads();

    // inverse chain 1 (Cb <-> B, result in B): analytic ch1
    ifft_tail(Cb, B, tw, tid);
    float2* __restrict__ d1 = d0 + S_LEN;
    for (int i = tid; i < S_LEN; i += FFT_THREADS)
        d1[i] = B[i];
}

// ---------------------------------------------------------------------------
// Kernel 2: pairwise sign counting (anchor structure; ONE delta: the
// ballot+popc positive-count is replaced by a sign-bit NEGATIVE-count,
//   acc += __float_as_uint(cross) >> 31
// (SHF+IADD on the alu pipe overlapping FMUL/FFMA on fma; no VOTE), plus a
// HW REDUX warp-sum before the unchanged lane-0 atomics. finalize's
// |2c - S|/S is invariant under P-counts vs N-counts (symmetry of abs).
// ---------------------------------------------------------------------------
__global__ __launch_bounds__(PLI_THREADS)
void pli_kernel() {
    extern __shared__ float2 sdata[];                 // [NCH][CHUNK]
    const int sc  = blockIdx.x;
    const int b   = blockIdx.y;
    const int tid = threadIdx.x;

    const float4* gsrc = reinterpret_cast<const float4*>(g_analytic);
    float4* ssh = reinterpret_cast<float4*>(sdata);
    for (int k = tid; k < NCH * (CHUNK / 2); k += PLI_THREADS) {
        int c  = k / (CHUNK / 2);
        int sp = k - c * (CHUNK / 2);
        size_t gi = (((size_t)(b * NCH + c)) * S_LEN + (size_t)sc * CHUNK) / 2 + sp;
        ssh[c * (CHUNK / 2) + sp] = gsrc[gi];
    }
    __syncthreads();

    const int warp = tid >> 5;
    const int lane = tid & 31;

    for (int t = warp; t < 136; t += NWARPS) {
        int ti = 0, rem = t;
        while (rem >= (16 - ti)) { rem -= (16 - ti); ti++; }
        int tj = ti + rem;

        const float2* rowi = sdata + (ti * 4) * CHUNK;
        const float2* rowj = sdata + (tj * 4) * CHUNK;

        unsigned acc[16];
        #pragma unroll
        for (int q = 0; q < 16; q++) acc[q] = 0u;

        #pragma unroll
        for (int it = 0; it < CHUNK / 32; it++) {
            int s = it * 32 + lane;
            float2 ai[4], aj[4];
            #pragma unroll
            for (int a = 0; a < 4; a++) ai[a] = rowi[a * CHUNK + s];
            #pragma unroll
            for (int a = 0; a < 4; a++) aj[a] = rowj[a * CHUNK + s];

            #pragma unroll
            for (int a = 0; a < 4; a++) {
                #pragma unroll
                for (int c2 = 0; c2 < 4; c2++) {
                    float p     = ai[a].x * aj[c2].y;
                    float cross = fmaf(ai[a].y, aj[c2].x, -p);
                    // negative (sign bit) => sin < 0 ; exact zeros measure-zero
                    acc[a * 4 + c2] += __float_as_uint(cross) >> 31;
                }
            }
        }

        // HW warp reduction, then unchanged lane-0 atomic epilogue
        #pragma unroll
        for (int q = 0; q < 16; q++)
            acc[q] = __reduce_add_sync(0xffffffffu, acc[q]);

        if (lane == 0) {
            #pragma unroll
            for (int a = 0; a < 4; a++) {
                #pragma unroll
                for (int c2 = 0; c2 < 4; c2++) {
                    atomicAdd(&g_cnt[(b * NCH + ti * 4 + a) * NCH + tj * 4 + c2],
                              (int)acc[a * 4 + c2]);
                }
            }
        }
    }
}

// ---------------------------------------------------------------------------
// Kernel 3: finalize |2c - S|/S ; zero diagonal; mirror i>j.
// (c = negative-count N here; |2N - S| == |sumsign| since sum = S - 2N.)
// ---------------------------------------------------------------------------
__global__ void finalize_kernel(float* __restrict__ out) {
    int idx = blockIdx.x * blockDim.x + threadIdx.x;
    if (idx >= NB * NCH * NCH) return;
    int b = idx >> 12;
    int i = (idx >> 6) & 63;
    int j = idx & 63;
    float v = 0.0f;
    if (i != j) {
        int c = (i < j) ? g_cnt[(b * NCH + i) * NCH + j]
                        : g_cnt[(b * NCH + j) * NCH + i];
        v = fabsf(2.0f * (float)c - (float)S_LEN) * (1.0f / (float)S_LEN);
    }
    out[idx] = v;
}

// ---------------------------------------------------------------------------
extern "C" void kernel_launch(void* const* d_in, const int* in_sizes, int n_in,
                              void* d_out, int out_size) {
    const float* x = (const float*)d_in[0];
    float* out = (float*)d_out;
    (void)in_sizes; (void)n_in; (void)out_size;

    const int pli_smem = NCH * CHUNK * (int)sizeof(float2);   // 64 KB
    cudaFuncSetAttribute(pli_kernel,
                         cudaFuncAttributeMaxDynamicSharedMemorySize, pli_smem);

    hilbert_kernel<<<NB * NCH / 2, FFT_THREADS>>>(x);
    pli_kernel<<<dim3(NSC, NB), PLI_THREADS, pli_smem>>>();
    finalize_kernel<<<(NB * NCH * NCH + 255) / 256, 256>>>(out);
}